// round 2
// baseline (speedup 1.0000x reference)
#include <cuda_runtime.h>
#include <math.h>
#include <stdint.h>

#define NPTS    8192
#define NB      2
#define QCHUNK  256
#define SEG     1024
#define NSEG    (NPTS / SEG)      // 8
#define NQCHUNK (NPTS / QCHUNK)   // 32
#define NQ_TOTAL (2 * NB * NPTS)  // 32768
#define NN_BLOCKS (2 * NB * NQCHUNK * NSEG)  // 1024
#define LOSS_BLOCKS (NQ_TOTAL / QCHUNK)      // 128

// Scratch (no device allocation allowed): keys pack (ordered score bits << 32 | idx)
__device__ unsigned long long g_keys[NQ_TOTAL];
__device__ int                g_counts[NQ_TOTAL];
__device__ double             g_partials[LOSS_BLOCKS];

// ---------------------------------------------------------------------------
// Kernel 1: init keys to +inf-equivalent, counts to zero
// ---------------------------------------------------------------------------
__global__ void dacd_init_kernel() {
    int i = blockIdx.x * blockDim.x + threadIdx.x;
    if (i < NQ_TOTAL) {
        g_keys[i]   = 0xFFFFFFFFFFFFFFFFULL;
        g_counts[i] = 0;
    }
}

// ---------------------------------------------------------------------------
// Kernel 2: nearest-neighbor scan.
// score(q, m) = ||c_m||^2 - 2 * <x_q, c_m>   (xx_q constant -> same argmin)
// Each block: 256 query points x 1024 candidate segment (SMEM float4 tile).
// Register-local (score, idx) min, then one packed atomicMin per thread.
// ---------------------------------------------------------------------------
__global__ __launch_bounds__(QCHUNK) void dacd_nn_kernel(
    const float* __restrict__ x, const float* __restrict__ gt)
{
    __shared__ float4 tile[SEG];

    const int blk = blockIdx.x;
    const int seg = blk & (NSEG - 1);          // bits [0,3)
    const int qc  = (blk >> 3) & (NQCHUNK - 1);// bits [3,8)
    const int b   = (blk >> 8) & 1;            // bit 8
    const int dir = (blk >> 9) & 1;            // bit 9

    const float* qry = dir ? gt : x;   // dir 0: x -> gt ; dir 1: gt -> x
    const float* cnd = dir ? x : gt;

    const float* c0p = cnd + (b * 3 + 0) * NPTS + seg * SEG;
    const float* c1p = cnd + (b * 3 + 1) * NPTS + seg * SEG;
    const float* c2p = cnd + (b * 3 + 2) * NPTS + seg * SEG;

    // Cooperative tile load: (c0, c1, c2, ||c||^2)
    for (int m = threadIdx.x; m < SEG; m += QCHUNK) {
        float c0 = c0p[m], c1 = c1p[m], c2 = c2p[m];
        tile[m] = make_float4(c0, c1, c2, fmaf(c0, c0, fmaf(c1, c1, c2 * c2)));
    }
    __syncthreads();

    const int q = qc * QCHUNK + threadIdx.x;
    const float x0 = qry[(b * 3 + 0) * NPTS + q];
    const float x1 = qry[(b * 3 + 1) * NPTS + q];
    const float x2 = qry[(b * 3 + 2) * NPTS + q];
    const float n0 = -2.0f * x0;
    const float n1 = -2.0f * x1;
    const float n2 = -2.0f * x2;

    float best = __int_as_float(0x7f800000);  // +inf
    int   bidx = 0;

#pragma unroll 8
    for (int m = 0; m < SEG; m++) {
        float4 c = tile[m];
        float s = fmaf(n0, c.x, fmaf(n1, c.y, fmaf(n2, c.z, c.w)));
        if (s < best) { best = s; bidx = m; }
    }

    // Order-preserving float -> uint map (score can be negative)
    unsigned u = __float_as_uint(best);
    u ^= (u >> 31) ? 0xFFFFFFFFu : 0x80000000u;
    unsigned long long key =
        ((unsigned long long)u << 32) | (unsigned)(seg * SEG + bidx);

    atomicMin(&g_keys[(dir * NB + b) * NPTS + q], key);
}

// ---------------------------------------------------------------------------
// Kernel 3: NN-count histogram. counts[(dir,b)][cand_idx] += 1
// ---------------------------------------------------------------------------
__global__ void dacd_count_kernel() {
    int i = blockIdx.x * blockDim.x + threadIdx.x;
    if (i < NQ_TOTAL) {
        unsigned idx = (unsigned)(g_keys[i] & 0xFFFFFFFFu);
        int base = i & ~(NPTS - 1);
        atomicAdd(&g_counts[base + idx], 1);
    }
}

// ---------------------------------------------------------------------------
// Kernel 4: per-query loss term, deterministic block reduction.
// term = 1 - exp(-10 * dist) / (count + 1e-6)   (frac_12 = frac_21 = 1)
// dist = xx + score  (recovered from packed key), in fp64 like the reference.
// ---------------------------------------------------------------------------
__global__ __launch_bounds__(QCHUNK) void dacd_loss_kernel(
    const float* __restrict__ x, const float* __restrict__ gt)
{
    __shared__ double sdata[QCHUNK];

    const int i   = blockIdx.x * QCHUNK + threadIdx.x;
    const int q   = i & (NPTS - 1);
    const int b   = (i >> 13) & 1;
    const int dir = (i >> 14) & 1;

    const float* qry = dir ? gt : x;

    unsigned long long key = g_keys[i];
    unsigned u = (unsigned)(key >> 32);
    unsigned orig = (u >> 31) ? (u ^ 0x80000000u) : ~u;
    float score = __uint_as_float(orig);

    float x0 = qry[(b * 3 + 0) * NPTS + q];
    float x1 = qry[(b * 3 + 1) * NPTS + q];
    float x2 = qry[(b * 3 + 2) * NPTS + q];
    double xx = (double)x0 * x0 + (double)x1 * x1 + (double)x2 * x2;
    double dist = xx + (double)score;

    int cnt = g_counts[(i & ~(NPTS - 1)) + (unsigned)(key & 0xFFFFFFFFu)];
    double w = 1.0 / ((double)cnt + 1e-6);
    double term = 1.0 - exp(-10.0 * dist) * w;

    sdata[threadIdx.x] = term;
    __syncthreads();
#pragma unroll
    for (int s = QCHUNK / 2; s > 0; s >>= 1) {
        if (threadIdx.x < s) sdata[threadIdx.x] += sdata[threadIdx.x + s];
        __syncthreads();
    }
    if (threadIdx.x == 0) g_partials[blockIdx.x] = sdata[0];
}

// ---------------------------------------------------------------------------
// Kernel 5: final deterministic sum of 128 partials -> scalar output.
// mean_b((loss1 + loss2)/2) = sum(all terms) / (NPTS * 2 * B)
// Output buffer dtype is float32 (scalar).
// ---------------------------------------------------------------------------
__global__ void dacd_final_kernel(float* __restrict__ out) {
    if (threadIdx.x == 0 && blockIdx.x == 0) {
        double s = 0.0;
        for (int i = 0; i < LOSS_BLOCKS; i++) s += g_partials[i];
        out[0] = (float)(s / (double)(NPTS * 2 * NB));
    }
}

extern "C" void kernel_launch(void* const* d_in, const int* in_sizes, int n_in,
                              void* d_out, int out_size) {
    const float* x  = (const float*)d_in[0];
    const float* gt = (const float*)d_in[1];
    float* out = (float*)d_out;

    dacd_init_kernel<<<(NQ_TOTAL + 255) / 256, 256>>>();
    dacd_nn_kernel<<<NN_BLOCKS, QCHUNK>>>(x, gt);
    dacd_count_kernel<<<(NQ_TOTAL + 255) / 256, 256>>>();
    dacd_loss_kernel<<<LOSS_BLOCKS, QCHUNK>>>(x, gt);
    dacd_final_kernel<<<1, 32>>>(out);
}

// round 3
// speedup vs baseline: 1.0803x; 1.0803x over previous
#include <cuda_runtime.h>
#include <math.h>
#include <stdint.h>

#define NPTS    8192
#define NB      2
#define QCHUNK  256
#define SEG     1024
#define NSEG    (NPTS / SEG)      // 8
#define NQCHUNK (NPTS / QCHUNK)   // 32
#define NQ_TOTAL (2 * NB * NPTS)  // 32768
#define NN_BLOCKS (2 * NB * NQCHUNK * NSEG)  // 1024
#define LOSS_BLOCKS (NQ_TOTAL / QCHUNK)      // 128

// Scratch: keys pack (ordered score bits << 32 | idx)
__device__ unsigned long long g_keys[NQ_TOTAL];
__device__ int                g_counts[NQ_TOTAL];
__device__ double             g_partials[LOSS_BLOCKS];

// ---- f32x2 packed helpers (sm_103a) --------------------------------------
__device__ __forceinline__ unsigned long long ffma2(
    unsigned long long a, unsigned long long b, unsigned long long c) {
    unsigned long long d;
    asm("fma.rn.f32x2 %0, %1, %2, %3;" : "=l"(d) : "l"(a), "l"(b), "l"(c));
    return d;
}
__device__ __forceinline__ unsigned long long fdup2(float v) {
    unsigned long long r;
    asm("mov.b64 %0, {%1, %1};" : "=l"(r) : "f"(v));
    return r;
}
__device__ __forceinline__ float2 unpack2(unsigned long long v) {
    float2 r;
    asm("mov.b64 {%0, %1}, %2;" : "=f"(r.x), "=f"(r.y) : "l"(v));
    return r;
}

// ---------------------------------------------------------------------------
// Kernel 1: init keys to max, counts to zero
// ---------------------------------------------------------------------------
__global__ void dacd_init_kernel() {
    int i = blockIdx.x * blockDim.x + threadIdx.x;
    if (i < NQ_TOTAL) {
        g_keys[i]   = 0xFFFFFFFFFFFFFFFFULL;
        g_counts[i] = 0;
    }
}

// ---------------------------------------------------------------------------
// Kernel 2: nearest-neighbor scan.
// score(q, m) = ||c_m||^2 - 2 <x_q, c_m>  (same argmin as full sq-dist)
// SoA SMEM tile; groups of 4 candidates:
//   4x LDS.128 + 6x FFMA2 + 3x FMNMX (group-min tree) + FSETP/FMNMX/SEL track.
// Winning group's intra-index recovered once per thread in the epilogue by
// bit-identical recomputation. Cross-segment merge by packed u64 atomicMin
// (keeps lowest index on score ties, matching reference argmin).
// ---------------------------------------------------------------------------
__global__ __launch_bounds__(QCHUNK) void dacd_nn_kernel(
    const float* __restrict__ x, const float* __restrict__ gt)
{
    __shared__ __align__(16) float sc0[SEG];
    __shared__ __align__(16) float sc1[SEG];
    __shared__ __align__(16) float sc2[SEG];
    __shared__ __align__(16) float sw [SEG];

    const int blk = blockIdx.x;
    const int seg = blk & (NSEG - 1);
    const int qc  = (blk >> 3) & (NQCHUNK - 1);
    const int b   = (blk >> 8) & 1;
    const int dir = (blk >> 9) & 1;

    const float* qry = dir ? gt : x;
    const float* cnd = dir ? x : gt;

    const float* c0p = cnd + (b * 3 + 0) * NPTS + seg * SEG;
    const float* c1p = cnd + (b * 3 + 1) * NPTS + seg * SEG;
    const float* c2p = cnd + (b * 3 + 2) * NPTS + seg * SEG;

    for (int m = threadIdx.x; m < SEG; m += QCHUNK) {
        float c0 = c0p[m], c1 = c1p[m], c2 = c2p[m];
        sc0[m] = c0; sc1[m] = c1; sc2[m] = c2;
        sw[m]  = fmaf(c0, c0, fmaf(c1, c1, c2 * c2));
    }
    __syncthreads();

    const int q = qc * QCHUNK + threadIdx.x;
    const float x0 = qry[(b * 3 + 0) * NPTS + q];
    const float x1 = qry[(b * 3 + 1) * NPTS + q];
    const float x2 = qry[(b * 3 + 2) * NPTS + q];

    const unsigned long long n0x2 = fdup2(-2.0f * x0);
    const unsigned long long n1x2 = fdup2(-2.0f * x1);
    const unsigned long long n2x2 = fdup2(-2.0f * x2);

    float best = __int_as_float(0x7f800000);  // +inf
    int   bg   = 0;                            // winning group-of-4

#pragma unroll 2
    for (int g = 0; g < SEG / 4; g++) {
        const int m = g * 4;
        ulonglong2 C0 = *(const ulonglong2*)(sc0 + m);
        ulonglong2 C1 = *(const ulonglong2*)(sc1 + m);
        ulonglong2 C2 = *(const ulonglong2*)(sc2 + m);
        ulonglong2 W  = *(const ulonglong2*)(sw  + m);

        unsigned long long t0 = ffma2(n2x2, C2.x, W.x);
        t0 = ffma2(n1x2, C1.x, t0);
        t0 = ffma2(n0x2, C0.x, t0);
        unsigned long long t1 = ffma2(n2x2, C2.y, W.y);
        t1 = ffma2(n1x2, C1.y, t1);
        t1 = ffma2(n0x2, C0.y, t1);

        float2 a = unpack2(t0);
        float2 c = unpack2(t1);
        float gm = fminf(fminf(a.x, a.y), fminf(c.x, c.y));

        bool p = gm < best;          // strict: earlier group wins ties
        best = fminf(best, gm);
        bg   = p ? g : bg;
    }

    // Epilogue: recover index within winning group (bit-identical recompute).
    {
        const int m = bg * 4;
        ulonglong2 C0 = *(const ulonglong2*)(sc0 + m);
        ulonglong2 C1 = *(const ulonglong2*)(sc1 + m);
        ulonglong2 C2 = *(const ulonglong2*)(sc2 + m);
        ulonglong2 W  = *(const ulonglong2*)(sw  + m);

        unsigned long long t0 = ffma2(n2x2, C2.x, W.x);
        t0 = ffma2(n1x2, C1.x, t0);
        t0 = ffma2(n0x2, C0.x, t0);
        unsigned long long t1 = ffma2(n2x2, C2.y, W.y);
        t1 = ffma2(n1x2, C1.y, t1);
        t1 = ffma2(n0x2, C0.y, t1);

        float2 a = unpack2(t0);
        float2 c = unpack2(t1);

        int jj = (a.x <= best) ? 0 :
                 (a.y <= best) ? 1 :
                 (c.x <= best) ? 2 : 3;   // first index hitting the min

        unsigned u = __float_as_uint(best);
        u ^= (u >> 31) ? 0xFFFFFFFFu : 0x80000000u;   // order-preserving map
        unsigned long long key =
            ((unsigned long long)u << 32) | (unsigned)(seg * SEG + m + jj);

        atomicMin(&g_keys[(dir * NB + b) * NPTS + q], key);
    }
}

// ---------------------------------------------------------------------------
// Kernel 3: NN-count histogram
// ---------------------------------------------------------------------------
__global__ void dacd_count_kernel() {
    int i = blockIdx.x * blockDim.x + threadIdx.x;
    if (i < NQ_TOTAL) {
        unsigned idx = (unsigned)(g_keys[i] & 0xFFFFFFFFu);
        int base = i & ~(NPTS - 1);
        atomicAdd(&g_counts[base + idx], 1);
    }
}

// ---------------------------------------------------------------------------
// Kernel 4: per-query loss (fp32 expf — error << 1e-3 budget),
// deterministic double block reduction.
// ---------------------------------------------------------------------------
__global__ __launch_bounds__(QCHUNK) void dacd_loss_kernel(
    const float* __restrict__ x, const float* __restrict__ gt)
{
    __shared__ double sdata[QCHUNK];

    const int i   = blockIdx.x * QCHUNK + threadIdx.x;
    const int q   = i & (NPTS - 1);
    const int b   = (i >> 13) & 1;
    const int dir = (i >> 14) & 1;

    const float* qry = dir ? gt : x;

    unsigned long long key = g_keys[i];
    unsigned u = (unsigned)(key >> 32);
    unsigned orig = (u >> 31) ? (u ^ 0x80000000u) : ~u;
    float score = __uint_as_float(orig);

    float x0 = qry[(b * 3 + 0) * NPTS + q];
    float x1 = qry[(b * 3 + 1) * NPTS + q];
    float x2 = qry[(b * 3 + 2) * NPTS + q];
    float xx = fmaf(x0, x0, fmaf(x1, x1, x2 * x2));
    float dist = xx + score;

    int cnt = g_counts[(i & ~(NPTS - 1)) + (unsigned)(key & 0xFFFFFFFFu)];
    float w = 1.0f / ((float)cnt + 1e-6f);
    float term = 1.0f - expf(-10.0f * dist) * w;

    sdata[threadIdx.x] = (double)term;
    __syncthreads();
#pragma unroll
    for (int s = QCHUNK / 2; s > 0; s >>= 1) {
        if (threadIdx.x < s) sdata[threadIdx.x] += sdata[threadIdx.x + s];
        __syncthreads();
    }
    if (threadIdx.x == 0) g_partials[blockIdx.x] = sdata[0];
}

// ---------------------------------------------------------------------------
// Kernel 5: final deterministic sum -> scalar fp32 output
// ---------------------------------------------------------------------------
__global__ void dacd_final_kernel(float* __restrict__ out) {
    if (threadIdx.x == 0 && blockIdx.x == 0) {
        double s = 0.0;
        for (int i = 0; i < LOSS_BLOCKS; i++) s += g_partials[i];
        out[0] = (float)(s / (double)(NPTS * 2 * NB));
    }
}

extern "C" void kernel_launch(void* const* d_in, const int* in_sizes, int n_in,
                              void* d_out, int out_size) {
    const float* x  = (const float*)d_in[0];
    const float* gt = (const float*)d_in[1];
    float* out = (float*)d_out;

    dacd_init_kernel<<<(NQ_TOTAL + 255) / 256, 256>>>();
    dacd_nn_kernel<<<NN_BLOCKS, QCHUNK>>>(x, gt);
    dacd_count_kernel<<<(NQ_TOTAL + 255) / 256, 256>>>();
    dacd_loss_kernel<<<LOSS_BLOCKS, QCHUNK>>>(x, gt);
    dacd_final_kernel<<<1, 32>>>(out);
}

// round 4
// speedup vs baseline: 1.2921x; 1.1961x over previous
#include <cuda_runtime.h>
#include <math.h>
#include <stdint.h>

#define NPTS    8192
#define NB      2
#define THREADS 256
#define QPT     2                         // queries per thread
#define QCHUNK  (THREADS * QPT)           // 512 queries per block
#define SEG     1024
#define NSEG    (NPTS / SEG)              // 8
#define NQCHUNK (NPTS / QCHUNK)           // 16
#define NQ_TOTAL (2 * NB * NPTS)          // 32768
#define NN_BLOCKS (2 * NB * NQCHUNK * NSEG)  // 512
#define LOSS_BLOCKS (NQ_TOTAL / THREADS)     // 128

// Scratch: keys pack (ordered score bits << 32 | idx)
__device__ unsigned long long g_keys[NQ_TOTAL];
__device__ int                g_counts[NQ_TOTAL];
__device__ double             g_partials[LOSS_BLOCKS];

// ---- f32x2 packed helpers (sm_103a) --------------------------------------
__device__ __forceinline__ unsigned long long ffma2(
    unsigned long long a, unsigned long long b, unsigned long long c) {
    unsigned long long d;
    asm("fma.rn.f32x2 %0, %1, %2, %3;" : "=l"(d) : "l"(a), "l"(b), "l"(c));
    return d;
}
__device__ __forceinline__ unsigned long long fdup2(float v) {
    unsigned long long r;
    asm("mov.b64 %0, {%1, %1};" : "=l"(r) : "f"(v));
    return r;
}
__device__ __forceinline__ float2 unpack2(unsigned long long v) {
    float2 r;
    asm("mov.b64 {%0, %1}, %2;" : "=f"(r.x), "=f"(r.y) : "l"(v));
    return r;
}

// ---------------------------------------------------------------------------
// Kernel 1: init keys to max, counts to zero
// ---------------------------------------------------------------------------
__global__ void dacd_init_kernel() {
    int i = blockIdx.x * blockDim.x + threadIdx.x;
    if (i < NQ_TOTAL) {
        g_keys[i]   = 0xFFFFFFFFFFFFFFFFULL;
        g_counts[i] = 0;
    }
}

// ---------------------------------------------------------------------------
// Kernel 2: nearest-neighbor scan. 2 queries/thread so each SMEM candidate
// load (4x LDS.128 per group-of-4) serves 8 pairs instead of 4 -> LDS-issue
// floor halves. Per group: 4 LDS + 12 FFMA2 + 6 FMNMX + 2x(FSETP/FMNMX/SEL).
// Group index of the min tracked; intra-group index recovered by bit-exact
// recompute in the epilogue. Cross-segment merge via packed u64 atomicMin
// (lowest index wins ties, matching reference argmin).
// ---------------------------------------------------------------------------
__global__ __launch_bounds__(THREADS) void dacd_nn_kernel(
    const float* __restrict__ x, const float* __restrict__ gt)
{
    __shared__ __align__(16) float sc0[SEG];
    __shared__ __align__(16) float sc1[SEG];
    __shared__ __align__(16) float sc2[SEG];
    __shared__ __align__(16) float sw [SEG];

    const int blk = blockIdx.x;
    const int seg = blk & (NSEG - 1);
    const int qc  = (blk >> 3) & (NQCHUNK - 1);
    const int b   = (blk >> 7) & 1;
    const int dir = (blk >> 8) & 1;

    const float* qry = dir ? gt : x;
    const float* cnd = dir ? x : gt;

    const float* c0p = cnd + (b * 3 + 0) * NPTS + seg * SEG;
    const float* c1p = cnd + (b * 3 + 1) * NPTS + seg * SEG;
    const float* c2p = cnd + (b * 3 + 2) * NPTS + seg * SEG;

    for (int m = threadIdx.x; m < SEG; m += THREADS) {
        float c0 = c0p[m], c1 = c1p[m], c2 = c2p[m];
        sc0[m] = c0; sc1[m] = c1; sc2[m] = c2;
        sw[m]  = fmaf(c0, c0, fmaf(c1, c1, c2 * c2));
    }
    __syncthreads();

    const int qA = qc * QCHUNK + threadIdx.x;
    const int qB = qA + THREADS;

    const float* qb = qry + b * 3 * NPTS;
    const unsigned long long a0 = fdup2(-2.0f * qb[0 * NPTS + qA]);
    const unsigned long long a1 = fdup2(-2.0f * qb[1 * NPTS + qA]);
    const unsigned long long a2 = fdup2(-2.0f * qb[2 * NPTS + qA]);
    const unsigned long long b0 = fdup2(-2.0f * qb[0 * NPTS + qB]);
    const unsigned long long b1 = fdup2(-2.0f * qb[1 * NPTS + qB]);
    const unsigned long long b2 = fdup2(-2.0f * qb[2 * NPTS + qB]);

    float bestA = __int_as_float(0x7f800000);
    float bestB = __int_as_float(0x7f800000);
    int bgA = 0, bgB = 0;

#pragma unroll 4
    for (int g = 0; g < SEG / 4; g++) {
        const int m = g * 4;
        ulonglong2 C0 = *(const ulonglong2*)(sc0 + m);
        ulonglong2 C1 = *(const ulonglong2*)(sc1 + m);
        ulonglong2 C2 = *(const ulonglong2*)(sc2 + m);
        ulonglong2 W  = *(const ulonglong2*)(sw  + m);

        // query A, 4 candidates
        unsigned long long tA0 = ffma2(a2, C2.x, W.x);
        tA0 = ffma2(a1, C1.x, tA0);
        tA0 = ffma2(a0, C0.x, tA0);
        unsigned long long tA1 = ffma2(a2, C2.y, W.y);
        tA1 = ffma2(a1, C1.y, tA1);
        tA1 = ffma2(a0, C0.y, tA1);
        float2 pa = unpack2(tA0);
        float2 qa = unpack2(tA1);
        float gmA = fminf(fminf(pa.x, pa.y), fminf(qa.x, qa.y));
        bool selA = gmA < bestA;       // strict: earlier group wins ties
        bestA = fminf(bestA, gmA);
        bgA   = selA ? g : bgA;

        // query B, same 4 candidates (no extra LDS)
        unsigned long long tB0 = ffma2(b2, C2.x, W.x);
        tB0 = ffma2(b1, C1.x, tB0);
        tB0 = ffma2(b0, C0.x, tB0);
        unsigned long long tB1 = ffma2(b2, C2.y, W.y);
        tB1 = ffma2(b1, C1.y, tB1);
        tB1 = ffma2(b0, C0.y, tB1);
        float2 pb = unpack2(tB0);
        float2 qbv = unpack2(tB1);
        float gmB = fminf(fminf(pb.x, pb.y), fminf(qbv.x, qbv.y));
        bool selB = gmB < bestB;
        bestB = fminf(bestB, gmB);
        bgB   = selB ? g : bgB;
    }

    const unsigned long long* keybase = g_keys + (dir * NB + b) * NPTS;

    // Epilogue A: recover intra-group index via bit-identical recompute
    {
        const int m = bgA * 4;
        ulonglong2 C0 = *(const ulonglong2*)(sc0 + m);
        ulonglong2 C1 = *(const ulonglong2*)(sc1 + m);
        ulonglong2 C2 = *(const ulonglong2*)(sc2 + m);
        ulonglong2 W  = *(const ulonglong2*)(sw  + m);
        unsigned long long t0 = ffma2(a2, C2.x, W.x);
        t0 = ffma2(a1, C1.x, t0);
        t0 = ffma2(a0, C0.x, t0);
        unsigned long long t1 = ffma2(a2, C2.y, W.y);
        t1 = ffma2(a1, C1.y, t1);
        t1 = ffma2(a0, C0.y, t1);
        float2 p = unpack2(t0);
        float2 r = unpack2(t1);
        int jj = (p.x <= bestA) ? 0 : (p.y <= bestA) ? 1 : (r.x <= bestA) ? 2 : 3;
        unsigned u = __float_as_uint(bestA);
        u ^= (u >> 31) ? 0xFFFFFFFFu : 0x80000000u;
        unsigned long long key =
            ((unsigned long long)u << 32) | (unsigned)(seg * SEG + m + jj);
        atomicMin((unsigned long long*)&keybase[qA], key);
    }
    // Epilogue B
    {
        const int m = bgB * 4;
        ulonglong2 C0 = *(const ulonglong2*)(sc0 + m);
        ulonglong2 C1 = *(const ulonglong2*)(sc1 + m);
        ulonglong2 C2 = *(const ulonglong2*)(sc2 + m);
        ulonglong2 W  = *(const ulonglong2*)(sw  + m);
        unsigned long long t0 = ffma2(b2, C2.x, W.x);
        t0 = ffma2(b1, C1.x, t0);
        t0 = ffma2(b0, C0.x, t0);
        unsigned long long t1 = ffma2(b2, C2.y, W.y);
        t1 = ffma2(b1, C1.y, t1);
        t1 = ffma2(b0, C0.y, t1);
        float2 p = unpack2(t0);
        float2 r = unpack2(t1);
        int jj = (p.x <= bestB) ? 0 : (p.y <= bestB) ? 1 : (r.x <= bestB) ? 2 : 3;
        unsigned u = __float_as_uint(bestB);
        u ^= (u >> 31) ? 0xFFFFFFFFu : 0x80000000u;
        unsigned long long key =
            ((unsigned long long)u << 32) | (unsigned)(seg * SEG + m + jj);
        atomicMin((unsigned long long*)&keybase[qB], key);
    }
}

// ---------------------------------------------------------------------------
// Kernel 3: NN-count histogram
// ---------------------------------------------------------------------------
__global__ void dacd_count_kernel() {
    int i = blockIdx.x * blockDim.x + threadIdx.x;
    if (i < NQ_TOTAL) {
        unsigned idx = (unsigned)(g_keys[i] & 0xFFFFFFFFu);
        int base = i & ~(NPTS - 1);
        atomicAdd(&g_counts[base + idx], 1);
    }
}

// ---------------------------------------------------------------------------
// Kernel 4: per-query loss, warp-shuffle deterministic reduction.
// ---------------------------------------------------------------------------
__global__ __launch_bounds__(THREADS) void dacd_loss_kernel(
    const float* __restrict__ x, const float* __restrict__ gt)
{
    __shared__ double swarp[THREADS / 32];

    const int i   = blockIdx.x * THREADS + threadIdx.x;
    const int q   = i & (NPTS - 1);
    const int b   = (i >> 13) & 1;
    const int dir = (i >> 14) & 1;

    const float* qry = dir ? gt : x;

    unsigned long long key = g_keys[i];
    unsigned u = (unsigned)(key >> 32);
    unsigned orig = (u >> 31) ? (u ^ 0x80000000u) : ~u;
    float score = __uint_as_float(orig);

    float x0 = qry[(b * 3 + 0) * NPTS + q];
    float x1 = qry[(b * 3 + 1) * NPTS + q];
    float x2 = qry[(b * 3 + 2) * NPTS + q];
    float xx = fmaf(x0, x0, fmaf(x1, x1, x2 * x2));
    float dist = xx + score;

    int cnt = g_counts[(i & ~(NPTS - 1)) + (unsigned)(key & 0xFFFFFFFFu)];
    float w = 1.0f / ((float)cnt + 1e-6f);
    double v = (double)(1.0f - expf(-10.0f * dist) * w);

#pragma unroll
    for (int off = 16; off > 0; off >>= 1)
        v += __shfl_down_sync(0xFFFFFFFFu, v, off);

    int lane = threadIdx.x & 31, wid = threadIdx.x >> 5;
    if (lane == 0) swarp[wid] = v;
    __syncthreads();
    if (wid == 0) {
        v = (lane < THREADS / 32) ? swarp[lane] : 0.0;
#pragma unroll
        for (int off = 4; off > 0; off >>= 1)
            v += __shfl_down_sync(0xFFFFFFFFu, v, off);
        if (lane == 0) g_partials[blockIdx.x] = v;
    }
}

// ---------------------------------------------------------------------------
// Kernel 5: final deterministic sum -> scalar fp32 output
// ---------------------------------------------------------------------------
__global__ void dacd_final_kernel(float* __restrict__ out) {
    if (threadIdx.x == 0 && blockIdx.x == 0) {
        double s = 0.0;
        for (int i = 0; i < LOSS_BLOCKS; i++) s += g_partials[i];
        out[0] = (float)(s / (double)(NPTS * 2 * NB));
    }
}

extern "C" void kernel_launch(void* const* d_in, const int* in_sizes, int n_in,
                              void* d_out, int out_size) {
    const float* x  = (const float*)d_in[0];
    const float* gt = (const float*)d_in[1];
    float* out = (float*)d_out;

    dacd_init_kernel<<<(NQ_TOTAL + 255) / 256, 256>>>();
    dacd_nn_kernel<<<NN_BLOCKS, THREADS>>>(x, gt);
    dacd_count_kernel<<<(NQ_TOTAL + 255) / 256, 256>>>();
    dacd_loss_kernel<<<LOSS_BLOCKS, THREADS>>>(x, gt);
    dacd_final_kernel<<<1, 32>>>(out);
}